// round 6
// baseline (speedup 1.0000x reference)
#include <cuda_runtime.h>
#include <cuda_bf16.h>
#include <cstdint>

// ---------------- problem constants ----------------
#define N_TOT 8192
#define D     128
#define IPC_C 512
#define ROW0  7680            // bz - IPC
#define NCOL  7680            // unmasked columns [0, 7680)
#define BM    128
#define BN    256
#define NTIL  (NCOL / BN)     // 30 column tiles
#define ETIL  (1024 / BN)     // tiles [0,4) = easy region (exact boundary)
#define NBLK  (NTIL * (IPC_C / BM))   // 120 blocks = one wave
#define LDF   128             // floats per smem row (XOR swizzle, no pad)
#define NROWS (BM + BN)       // 384 smem rows (A then B)

// ---------------- device globals ----------------
__device__ float g_part[NTIL * IPC_C];   // [colTile][row]
__device__ int   g_done;                 // zero-init; reset each replay

#define CP_ASYNC16(dst_u32, src_ptr) \
    asm volatile("cp.async.cg.shared.global [%0], [%1], 16;" \
                 :: "r"(dst_u32), "l"(src_ptr) : "memory")
#define CP_COMMIT()  asm volatile("cp.async.commit_group;" ::: "memory")
#define CP_WAIT0()   asm volatile("cp.async.wait_group 0;" ::: "memory")

__device__ __forceinline__ uint32_t to_tf32(float x) {
    uint32_t t;
    asm("cvt.rna.tf32.f32 %0, %1;" : "=r"(t) : "f"(x));
    return t;
}

// smem float index of group g (8 floats), row r, with XOR swizzle
__device__ __forceinline__ int sw_off(int r, int g) {
    return r * LDF + ((g ^ (r & 7)) << 3);
}

#define SMEM_FLOATS (NROWS * LDF)   // 49152 floats = 192 KB

// ---------------- fused kernel: stage -> norm/tf32/permute -> MMA -> max -> loss ----------------
// 512 threads = 16 warps, 4(m) x 4(n); warp tile 32x64 (mt=2, nt=8 of n8).
__global__ void __launch_bounds__(512, 1) hse_kernel(const float* __restrict__ fvec,
                                                     const float* __restrict__ a_scl,
                                                     float* __restrict__ out) {
    extern __shared__ float sm[];

    const int tid  = threadIdx.x;
    const int lane = tid & 31;
    const int w    = tid >> 5;
    const int wm   = w >> 2;        // 0..3 -> 32-row strip
    const int wn   = w & 3;         // 0..3 -> 64-col strip
    const int q    = lane >> 2;     // 0..7
    const int tig  = lane & 3;      // 0..3
    const int rowBase = ROW0 + blockIdx.y * BM;
    const int colBase = blockIdx.x * BN;

    const uint32_t sBase = (uint32_t)__cvta_generic_to_shared(sm);

    // ---- stage raw f32: rows [0,128)=A, [128,384)=B; 12288 float4 ----
    #pragma unroll
    for (int t = 0; t < 24; t++) {
        int idx = tid + t * 512;
        int r = idx >> 5, f4 = idx & 31;        // 32 float4 per row
        int g = f4 >> 1, h = f4 & 1;
        const float* src = (r < BM)
            ? fvec + (size_t)(rowBase + r) * D + f4 * 4
            : fvec + (size_t)(colBase + r - BM) * D + f4 * 4;
        CP_ASYNC16(sBase + (uint32_t)(sw_off(r, g) + h * 4) * 4, src);
    }
    CP_COMMIT();
    CP_WAIT0();
    __syncthreads();

    // ---- normalize + tf32 + K-permute in place ----
    // warp w owns rows [24w, 24w+24); lane: row = +it*2 + (lane>>4), group = lane&15
    #pragma unroll
    for (int it = 0; it < 12; it++) {
        int r = w * 24 + it * 2 + (lane >> 4);
        int g = lane & 15;
        float* p = sm + sw_off(r, g);
        float4 lo = *(float4*)p;         // k = 8g+0..3
        float4 hi = *(float4*)(p + 4);   // k = 8g+4..7
        float s = lo.x*lo.x + lo.y*lo.y + lo.z*lo.z + lo.w*lo.w
                + hi.x*hi.x + hi.y*hi.y + hi.z*hi.z + hi.w*hi.w;
        #pragma unroll
        for (int o = 1; o < 16; o <<= 1) s += __shfl_xor_sync(0xffffffffu, s, o);
        float inv = rsqrtf(s);
        if (!(s > 1e-24f)) inv = 1e12f;
        // permuted layout within group: [k0,k4,k1,k5,k2,k6,k3,k7]
        uint4 u0, u1;
        u0.x = to_tf32(lo.x * inv); u0.y = to_tf32(hi.x * inv);
        u0.z = to_tf32(lo.y * inv); u0.w = to_tf32(hi.y * inv);
        u1.x = to_tf32(lo.z * inv); u1.y = to_tf32(hi.z * inv);
        u1.z = to_tf32(lo.w * inv); u1.w = to_tf32(hi.w * inv);
        *(uint4*)p       = u0;
        *(uint4*)(p + 4) = u1;
    }
    __syncthreads();

    // ---- mainloop: 16 K-steps of m16n8k8 tf32; all fragment loads are LDS.64 ----
    float acc[2][8][4];
    #pragma unroll
    for (int mt = 0; mt < 2; mt++)
        #pragma unroll
        for (int nt = 0; nt < 8; nt++)
            #pragma unroll
            for (int e = 0; e < 4; e++) acc[mt][nt][e] = 0.f;

    const uint32_t* U = (const uint32_t*)sm;
    const int rA0 = wm * 32 + q;          // rA&7 == q for all mt offsets
    const int rB0 = BM + wn * 64 + q;     // rB&7 == q for all nt offsets

    #pragma unroll
    for (int s = 0; s < 16; s++) {
        const int go = (s ^ q) * 8 + 2 * tig;   // swizzled in-row float offset
        uint32_t af[2][4];
        #pragma unroll
        for (int mt = 0; mt < 2; mt++) {
            int r0 = rA0 + mt * 16;
            uint2 v0 = *(const uint2*)(U + r0 * LDF + go);        // (k, k+4) row q
            uint2 v1 = *(const uint2*)(U + (r0 + 8) * LDF + go);  // row q+8
            af[mt][0] = v0.x; af[mt][2] = v0.y;
            af[mt][1] = v1.x; af[mt][3] = v1.y;
        }
        uint32_t bf[8][2];
        #pragma unroll
        for (int nt = 0; nt < 8; nt++) {
            uint2 v = *(const uint2*)(U + (rB0 + nt * 8) * LDF + go);
            bf[nt][0] = v.x; bf[nt][1] = v.y;
        }
        #pragma unroll
        for (int mt = 0; mt < 2; mt++)
            #pragma unroll
            for (int nt = 0; nt < 8; nt++)
                asm volatile(
                    "mma.sync.aligned.m16n8k8.row.col.f32.tf32.tf32.f32 "
                    "{%0,%1,%2,%3}, {%4,%5,%6,%7}, {%8,%9}, {%0,%1,%2,%3};"
                    : "+f"(acc[mt][nt][0]), "+f"(acc[mt][nt][1]),
                      "+f"(acc[mt][nt][2]), "+f"(acc[mt][nt][3])
                    : "r"(af[mt][0]), "r"(af[mt][1]), "r"(af[mt][2]), "r"(af[mt][3]),
                      "r"(bf[nt][0]), "r"(bf[nt][1]));
    }
    __syncthreads();   // all smem reads done before reuse

    // ---- row max: thread -> quad shfl -> cross-warp via smem ----
    float* pm = sm;    // [4(wn)][128]
    #pragma unroll
    for (int mt = 0; mt < 2; mt++) {
        float mlo = -2.f, mhi = -2.f;
        #pragma unroll
        for (int nt = 0; nt < 8; nt++) {
            mlo = fmaxf(mlo, fmaxf(acc[mt][nt][0], acc[mt][nt][1]));
            mhi = fmaxf(mhi, fmaxf(acc[mt][nt][2], acc[mt][nt][3]));
        }
        #pragma unroll
        for (int o = 1; o < 4; o <<= 1) {
            mlo = fmaxf(mlo, __shfl_xor_sync(0xffffffffu, mlo, o));
            mhi = fmaxf(mhi, __shfl_xor_sync(0xffffffffu, mhi, o));
        }
        if (tig == 0) {
            int r = wm * 32 + mt * 16 + q;
            pm[wn * 128 + r]     = mlo;
            pm[wn * 128 + r + 8] = mhi;
        }
    }
    __syncthreads();

    if (tid < BM) {
        float m = fmaxf(fmaxf(pm[tid], pm[128 + tid]),
                        fmaxf(pm[256 + tid], pm[384 + tid]));
        g_part[blockIdx.x * IPC_C + blockIdx.y * BM + tid] = m;
    }
    __syncthreads();

    // ---- last-block-done fused finalize ----
    __shared__ int isLast;
    __shared__ float red[512];
    if (tid == 0) {
        __threadfence();
        isLast = (atomicAdd(&g_done, 1) == NBLK - 1);
    }
    __syncthreads();
    if (!isLast) return;
    if (tid == 0) __threadfence();
    __syncthreads();

    float e = -2.f, h = -2.f;
    #pragma unroll
    for (int j = 0; j < ETIL; j++)     e = fmaxf(e, g_part[j * IPC_C + tid]);
    #pragma unroll
    for (int j = ETIL; j < NTIL; j++)  h = fmaxf(h, g_part[j * IPC_C + tid]);
    red[tid] = log1pf(expf((h - e) * 10.0f));   // 1/SIGMA1 = 10
    __syncthreads();
    #pragma unroll
    for (int s2 = 256; s2; s2 >>= 1) {
        if (tid < s2) red[tid] += red[tid + s2];
        __syncthreads();
    }
    if (tid == 0) {
        out[0] = a_scl[0] * red[0] * (1.0f / 512.0f);
        g_done = 0;      // reset for the next graph replay
    }
}

extern "C" void kernel_launch(void* const* d_in, const int* in_sizes, int n_in,
                              void* d_out, int out_size) {
    const float* fvec = (const float*)d_in[0];   // [8192,128] f32
    // d_in[1] = Lvec (dead in the reference math)
    const float* a    = (const float*)d_in[2];   // scalar f32
    float* out = (float*)d_out;

    cudaFuncSetAttribute(hse_kernel,
                         cudaFuncAttributeMaxDynamicSharedMemorySize,
                         SMEM_FLOATS * 4);

    hse_kernel<<<dim3(NTIL, IPC_C / BM), 512, SMEM_FLOATS * 4>>>(fvec, a, out);
}